// round 1
// baseline (speedup 1.0000x reference)
#include <cuda_runtime.h>

#define BATCH 4
#define NLAB 8
#define VOX (64*160*160)        // 1,638,400 voxels per sample
#define V4  (VOX/4)             // 409,600 float4/int4 chunks

// Global accumulators (device scratch; no allocation allowed)
__device__ double             g_T[BATCH];          // total sum of p1 per batch
__device__ double             g_S[BATCH][NLAB];    // sum p1 per label 1..8
__device__ unsigned long long g_C[BATCH][NLAB];    // count per label 1..8

__global__ void zero_kernel() {
    int t = threadIdx.x;
    if (t < BATCH) g_T[t] = 0.0;
    if (t < BATCH * NLAB) {
        ((double*)g_S)[t] = 0.0;
        ((unsigned long long*)g_C)[t] = 0ull;
    }
}

__global__ __launch_bounds__(256) void reduce_kernel(const float* __restrict__ x,
                                                     const int* __restrict__ ml) {
    const int b = blockIdx.y;
    const float4* __restrict__ x0v = reinterpret_cast<const float4*>(x + (size_t)b * 2 * VOX);
    const float4* __restrict__ x1v = reinterpret_cast<const float4*>(x + (size_t)b * 2 * VOX + VOX);
    const int4*   __restrict__ mlv = reinterpret_cast<const int4*>(ml + (size_t)b * VOX);

    float tSum = 0.f;
    float s[NLAB];
    unsigned c[NLAB];
#pragma unroll
    for (int i = 0; i < NLAB; i++) { s[i] = 0.f; c[i] = 0u; }

    const int stride = gridDim.x * blockDim.x;
    for (int i = blockIdx.x * blockDim.x + threadIdx.x; i < V4; i += stride) {
        float4 a  = x0v[i];
        float4 bb = x1v[i];
        int4   l  = mlv[i];

        // p1 = sigmoid(x1 - x0) = 1 / (1 + exp(x0 - x1))
        float p0 = __fdividef(1.f, 1.f + __expf(a.x - bb.x));
        float p1 = __fdividef(1.f, 1.f + __expf(a.y - bb.y));
        float p2 = __fdividef(1.f, 1.f + __expf(a.z - bb.z));
        float p3 = __fdividef(1.f, 1.f + __expf(a.w - bb.w));

        tSum += (p0 + p1) + (p2 + p3);

        if ((l.x | l.y | l.z | l.w) != 0) {   // rare (~7% of voxels): blob labels
            float pv[4] = {p0, p1, p2, p3};
            int   lv[4] = {l.x, l.y, l.z, l.w};
#pragma unroll
            for (int j = 0; j < 4; j++) {
                int lab = lv[j];
#pragma unroll
                for (int L = 1; L <= NLAB; L++) {
                    if (lab == L) { s[L-1] += pv[j]; c[L-1]++; }
                }
            }
        }
    }

    // warp reduction
#pragma unroll
    for (int o = 16; o > 0; o >>= 1) {
        tSum += __shfl_xor_sync(0xffffffffu, tSum, o);
#pragma unroll
        for (int i = 0; i < NLAB; i++) {
            s[i] += __shfl_xor_sync(0xffffffffu, s[i], o);
            c[i] += __shfl_xor_sync(0xffffffffu, c[i], o);
        }
    }

    __shared__ float    shT;
    __shared__ float    shS[NLAB];
    __shared__ unsigned shC[NLAB];
    if (threadIdx.x == 0) shT = 0.f;
    if (threadIdx.x < NLAB) { shS[threadIdx.x] = 0.f; shC[threadIdx.x] = 0u; }
    __syncthreads();

    if ((threadIdx.x & 31) == 0) {
        atomicAdd(&shT, tSum);
#pragma unroll
        for (int i = 0; i < NLAB; i++) {
            atomicAdd(&shS[i], s[i]);
            atomicAdd(&shC[i], c[i]);
        }
    }
    __syncthreads();

    if (threadIdx.x == 0) atomicAdd(&g_T[b], (double)shT);
    if (threadIdx.x < NLAB) {
        atomicAdd(&g_S[b][threadIdx.x], (double)shS[threadIdx.x]);
        atomicAdd(&g_C[b][threadIdx.x], (unsigned long long)shC[threadIdx.x]);
    }
}

__global__ void finalize_kernel(float* __restrict__ out) {
    if (threadIdx.x != 0 || blockIdx.x != 0) return;
    const double A = 0.3, Bq = 0.7;       // TV_ALPHA, TV_BETA
    const double Vd = (double)VOX;
    double mainAcc = 0.0, blobAcc = 0.0;

    for (int b = 0; b < BATCH; b++) {
        double T = g_T[b];
        double S[NLAB], C[NLAB], sSum = 0.0, cSum = 0.0;
        for (int i = 0; i < NLAB; i++) {
            S[i] = g_S[b][i];
            C[i] = (double)g_C[b][i];
            sSum += S[i]; cSum += C[i];
        }
        double cnt0 = Vd - cSum;      // background voxel count
        double s0   = T - sSum;       // sum of p1 over background

        // ---- main loss (unmasked softmax), classes 1 and 0 ----
        {
            double tp = sSum, P = T, G = cSum;
            double den = tp + A * (P - tp) + Bq * (G - tp);
            den = den < 1e-8 ? 1e-8 : den;
            mainAcc += tp / den;

            double tp0 = cnt0 - s0, P0 = Vd - T, G0 = cnt0;
            double den0 = tp0 + A * (P0 - tp0) + Bq * (G0 - tp0);
            den0 = den0 < 1e-8 ? 1e-8 : den0;
            mainAcc += tp0 / den0;
        }

        // ---- blob losses: masked voxels (other blobs) get p = 0.5 exactly ----
        for (int k = 0; k < NLAB; k++) {
            double M = cSum - C[k];   // other-blob voxel count

            double tp = S[k];
            double P  = S[k] + s0 + 0.5 * M;
            double G  = C[k];
            double den = tp + A * (P - tp) + Bq * (G - tp);
            den = den < 1e-8 ? 1e-8 : den;
            blobAcc += tp / den;

            double tp0 = (cnt0 - s0) + 0.5 * M;
            double P0  = Vd - P;
            double G0  = Vd - C[k];
            double den0 = tp0 + A * (P0 - tp0) + Bq * (G0 - tp0);
            den0 = den0 < 1e-8 ? 1e-8 : den0;
            blobAcc += tp0 / den0;
        }
    }

    // main_loss = -mean over (B,C) of tversky;  weight = MAIN_WEIGHT*CRIT = 1.0
    double main_loss = -mainAcc / (2.0 * BATCH);
    // per blob element: 0.5 * (-(tv1+tv0)/2), mean over K*B  ->  -blobAcc/128
    double blob_loss = -0.25 * blobAcc / ((double)NLAB * BATCH);

    out[0] = (float)(main_loss + blob_loss);
}

extern "C" void kernel_launch(void* const* d_in, const int* in_sizes, int n_in,
                              void* d_out, int out_size) {
    const float* x  = (const float*)d_in[0];
    const int*   ml = (const int*)d_in[1];
    float* out = (float*)d_out;

    zero_kernel<<<1, 64>>>();
    dim3 grid(128, BATCH);
    reduce_kernel<<<grid, 256>>>(x, ml);
    finalize_kernel<<<1, 32>>>(out);
}